// round 10
// baseline (speedup 1.0000x reference)
#include <cuda_runtime.h>
#include <math.h>

// Problem constants (fixed shapes: z = (16, 128, 64, 64) fp32, codebook = (1024, 128) fp32)
#define CDIM    128
#define KCODES  1024
#define HWDIM   4096          // 64*64 pixels per batch image
#define NPIXMAX 65536         // 16 * 4096
#define PBLOCKS 1024          // quant partial blocks

// ---- scratch (no allocations allowed; __device__ globals are the sanctioned path) ----
__device__ float  g_zz[NPIXMAX];         // per-pixel sum(z^2), sequential fp32
__device__ float  g_ee[KCODES];          // per-code sum(e^2), sequential fp32
__device__ int    g_idx[NPIXMAX];        // argmin indices
__device__ int    g_counts[KCODES];      // code histogram
__device__ double g_partials[PBLOCKS];   // deterministic per-block loss partials
__device__ float  g_idx_scratch[NPIXMAX];// fallback index sink if out buffer too small

// ---- packed fp32x2 helpers (lanewise IEEE fp32 => numerics identical to scalar) ----
__device__ __forceinline__ unsigned long long dup_f32(float x) {
    unsigned long long r;
    asm("mov.b64 %0, {%1, %1};" : "=l"(r) : "f"(x));
    return r;
}
__device__ __forceinline__ void fma_f32x2(unsigned long long& d,
                                          unsigned long long a,
                                          unsigned long long b) {
    asm("fma.rn.f32x2 %0, %1, %2, %3;" : "=l"(d) : "l"(a), "l"(b), "l"(d));
}
__device__ __forceinline__ void unpack_f32x2(float& lo, float& hi, unsigned long long v) {
    asm("mov.b64 {%0, %1}, %2;" : "=f"(lo), "=f"(hi) : "l"(v));
}

// ------------------------------------------------------------------
__global__ void zero_counts_kernel() {
    int i = blockIdx.x * blockDim.x + threadIdx.x;
    if (i < KCODES) g_counts[i] = 0;
}

// ------------------------------------------------------------------
// zz[n] = sum_c fl(z[b,c,hw]^2), strictly sequential fp32 adds
// ------------------------------------------------------------------
__global__ void zz_kernel(const float* __restrict__ z, int npix) {
    int n = blockIdx.x * blockDim.x + threadIdx.x;
    if (n >= npix) return;
    int b  = n / HWDIM;
    int hw = n - b * HWDIM;
    const float* p = z + ((size_t)b * CDIM) * HWDIM + hw;
    float s = 0.0f;
#pragma unroll
    for (int c = 0; c < CDIM; c++) {
        float v = p[(size_t)c * HWDIM];
        s = __fadd_rn(s, __fmul_rn(v, v));   // no FMA, no reassociation
    }
    g_zz[n] = s;
}

// ------------------------------------------------------------------
__global__ void ee_kernel(const float* __restrict__ cb) {
    int k = blockIdx.x * blockDim.x + threadIdx.x;
    if (k >= KCODES) return;
    const float* p = cb + (size_t)k * CDIM;
    float s = 0.0f;
#pragma unroll
    for (int c = 0; c < CDIM; c++) {
        float v = p[c];
        s = __fadd_rn(s, __fmul_rn(v, v));
    }
    g_ee[k] = s;
}

// ------------------------------------------------------------------
// argmin: R9 skeleton (64 px x 1024 codes, 8-c double-buffered chunks,
// register-staged loads at distance 2, one barrier per chunk) with the
// f32x2 LANE ASSIGNMENT SWAPPED: the two fp32 lanes now hold two
// ADJACENT CODES (direct ulonglong2 LDS from es, zero packing movs);
// the pixel scalar is broadcast-duplicated (4 alu movs per ci).
//   warp lane = (pg in [0,4)) * 8 + (cg in [0,8))
//   warp tp: wp = tp&3 (pixel 16-tile), wc = tp>>2 (code 64-half)
//   thread: 4 pixels (wp*16+pg*4 ..+3) x 8 codes (cg*4..+3 and +32..)
// LDS per ci: z float4 broadcast (1 wf) + 2x LDS.128 codes with 16B
// stride, banks cg*4 mod 32 all distinct (1 wf each) => 3 wf vs R9's 6.
// Accumulation per (pixel,code): sequential ascending-c fp32 FMA chain
// (identical rounding to R1-R9). d2 = fl(fl(zz - fl(2*dot)) + ee);
// first-minimum (lowest k) tie-break at every combine step.
// ------------------------------------------------------------------
__global__ void __launch_bounds__(256) argmin_kernel(
        const float* __restrict__ z, const float* __restrict__ cb) {
    __shared__ __align__(16) float zs[2][8][64];    // [buf][c][pixel]  4KB
    __shared__ __align__(16) float es[2][8][132];   // [buf][c][code]   8.25KB (padded)
    __shared__ float ees[KCODES];                   // cached code norms 4KB
    __shared__ float redv[2][64];                   // cross-warp merge buffers
    __shared__ int   redi[2][64];

    const int tid  = threadIdx.x;
    const int lane = tid & 31;
    const int tp   = tid >> 5;
    const int wp   = tp & 3;                // pixel 16-tile of this warp
    const int wc   = tp >> 2;               // code half (0: k<64, 1: k>=64 within tile)
    const int pg   = lane >> 3;             // pixel group within warp
    const int cg   = lane & 7;              // code group within warp
    const int px_base = wp * 16 + pg * 4;   // first of this thread's 4 pixels

    const int n0  = blockIdx.x * 64;        // 4096 % 64 == 0 -> tile never straddles b
    const int b   = n0 >> 12;
    const int hw0 = n0 & (HWDIM - 1);
    const float* zbase = z + ((size_t)b * CDIM) * HWDIM + hw0;

    // loader geometry (identical to R9)
    const int zci = tid >> 6;               // 0..3 (rows zci and zci+4)
    const int zp  = tid & 63;
    const int kk  = tid >> 1;               // code 0..127 within tile
    const int h   = (tid & 1) * 4;          // c-half within chunk

    float zzr[4];
#pragma unroll
    for (int p = 0; p < 4; p++) zzr[p] = g_zz[n0 + px_base + p];

    float bestv[4];
    int   besti[4];
#pragma unroll
    for (int p = 0; p < 4; p++) { bestv[p] = 3.4e38f; besti[p] = 0x7fffffff; }

    // ---- prologue: chunk 0 ----
    float  zr0, zr1;
    float4 cbv;
    zr0 = zbase[(size_t)(0 + zci) * HWDIM + zp];
    zr1 = zbase[(size_t)(4 + zci) * HWDIM + zp];
    cbv = *(const float4*)(cb + (size_t)kk * CDIM + h);
    // cache ee in smem (covers the chunk-0 LDG latency)
#pragma unroll
    for (int i = 0; i < KCODES / 256; i++) ees[tid + i * 256] = g_ee[tid + i * 256];
    // store chunk 0 -> buffer 0 (one-time exposed latency)
    zs[0][zci][zp]     = zr0;
    zs[0][4 + zci][zp] = zr1;
    es[0][h + 0][kk] = cbv.x; es[0][h + 1][kk] = cbv.y;
    es[0][h + 2][kk] = cbv.z; es[0][h + 3][kk] = cbv.w;
    // stage chunk 1
    zr0 = zbase[(size_t)(8 + zci) * HWDIM + zp];
    zr1 = zbase[(size_t)(12 + zci) * HWDIM + zp];
    cbv = *(const float4*)(cb + (size_t)kk * CDIM + 8 + h);
    __syncthreads();                        // buffer 0 + ees visible

    unsigned long long acc[4][4];           // [pixel][code pair]
#pragma unroll
    for (int p = 0; p < 4; p++)
#pragma unroll
        for (int j = 0; j < 4; j++) acc[p][j] = 0ull;

#pragma unroll 1
    for (int g = 0; g < 128; g++) {
        const int buf = g & 1;
        // (1) store chunk g+1 from staged regs (data already arrived)
        if (g + 1 < 128) {
            const int nb = 1 - buf;
            zs[nb][zci][zp]     = zr0;
            zs[nb][4 + zci][zp] = zr1;
            es[nb][h + 0][kk] = cbv.x; es[nb][h + 1][kk] = cbv.y;
            es[nb][h + 2][kk] = cbv.z; es[nb][h + 3][kk] = cbv.w;
        }
        // (2) issue LDG for chunk g+2 (covered by this iteration's compute)
        if (g + 2 < 128) {
            const int g2  = g + 2;
            const int c02 = (g2 & 15) * 8;
            const int kt2 = g2 >> 4;
            zr0 = zbase[(size_t)(c02 + zci) * HWDIM + zp];
            zr1 = zbase[(size_t)(c02 + 4 + zci) * HWDIM + zp];
            cbv = *(const float4*)(cb + (size_t)(kt2 * 128 + kk) * CDIM + c02 + h);
        }
        // (3) compute chunk g: codes packed in f32x2 lanes, pixels dup'd
#pragma unroll
        for (int ci = 0; ci < 8; ci++) {
            float4 zf = *(const float4*)&zs[buf][ci][px_base];          // bcast, 1 wf
            // two 4-code groups at +0 and +32 codes: units cg and cg+8
            ulonglong2 ea = *(const ulonglong2*)&es[buf][ci][wc * 64 + cg * 4];       // 1 wf
            ulonglong2 eb = *(const ulonglong2*)&es[buf][ci][wc * 64 + 32 + cg * 4];  // 1 wf
            unsigned long long z0 = dup_f32(zf.x);
            unsigned long long z1 = dup_f32(zf.y);
            unsigned long long z2 = dup_f32(zf.z);
            unsigned long long z3 = dup_f32(zf.w);
            fma_f32x2(acc[0][0], z0, ea.x); fma_f32x2(acc[0][1], z0, ea.y);
            fma_f32x2(acc[0][2], z0, eb.x); fma_f32x2(acc[0][3], z0, eb.y);
            fma_f32x2(acc[1][0], z1, ea.x); fma_f32x2(acc[1][1], z1, ea.y);
            fma_f32x2(acc[1][2], z1, eb.x); fma_f32x2(acc[1][3], z1, eb.y);
            fma_f32x2(acc[2][0], z2, ea.x); fma_f32x2(acc[2][1], z2, ea.y);
            fma_f32x2(acc[2][2], z2, eb.x); fma_f32x2(acc[2][3], z2, eb.y);
            fma_f32x2(acc[3][0], z3, ea.x); fma_f32x2(acc[3][1], z3, ea.y);
            fma_f32x2(acc[3][2], z3, eb.x); fma_f32x2(acc[3][3], z3, eb.y);
        }
        // (4) end of a 128-code tile? score + reset accumulators.
        //     Per-pixel scan order is ascending k: cp0 (kb,kb+1), cp1 (+2,+3),
        //     cp2 (+32,+33), cp3 (+34,+35); strict < keeps first minimum.
        if ((g & 15) == 15) {
            const int kb = (g >> 4) * 128 + wc * 64 + cg * 4;
#pragma unroll
            for (int cp = 0; cp < 4; cp++) {
                const int klo = kb + ((cp < 2) ? cp * 2 : 32 + (cp - 2) * 2);
                const float eelo = ees[klo];
                const float eehi = ees[klo + 1];
#pragma unroll
                for (int p = 0; p < 4; p++) {
                    float dlo, dhi;
                    unpack_f32x2(dlo, dhi, acc[p][cp]);
                    float d2lo = __fadd_rn(__fsub_rn(zzr[p], __fmul_rn(2.0f, dlo)), eelo);
                    float d2hi = __fadd_rn(__fsub_rn(zzr[p], __fmul_rn(2.0f, dhi)), eehi);
                    if (d2lo < bestv[p]) { bestv[p] = d2lo; besti[p] = klo; }
                    if (d2hi < bestv[p]) { bestv[p] = d2hi; besti[p] = klo + 1; }
                    acc[p][cp] = 0ull;
                }
            }
        }
        __syncthreads();   // single barrier per chunk
    }

    // reduce over the 8 cg lanes (xor stays within the cg dimension);
    // tie -> smaller index (jnp.argmin first-occurrence)
#pragma unroll
    for (int off = 1; off < 8; off <<= 1) {
#pragma unroll
        for (int p = 0; p < 4; p++) {
            float ov = __shfl_xor_sync(0xffffffffu, bestv[p], off);
            int   oi = __shfl_xor_sync(0xffffffffu, besti[p], off);
            if (ov < bestv[p] || (ov == bestv[p] && oi < besti[p])) {
                bestv[p] = ov; besti[p] = oi;
            }
        }
    }
    if (cg == 0) {
#pragma unroll
        for (int p = 0; p < 4; p++) {
            redv[wc][px_base + p] = bestv[p];
            redi[wc][px_base + p] = besti[p];
        }
    }
    __syncthreads();
    // merge the two code halves (deterministic; tie -> smaller index)
    if (tid < 64) {
        float v0 = redv[0][tid], v1 = redv[1][tid];
        int   i0 = redi[0][tid], i1 = redi[1][tid];
        int use1 = (v1 < v0) || (v1 == v0 && i1 < i0);
        g_idx[n0 + tid] = use1 ? i1 : i0;
    }
}

// ------------------------------------------------------------------
// gather + straight-through output + deterministic loss partials.
// ------------------------------------------------------------------
__global__ void __launch_bounds__(256) quant_kernel(
        const float* __restrict__ z, const float* __restrict__ cb,
        float* __restrict__ outq, int total) {
    __shared__ double sh[8];
    double sq = 0.0;
    const int stride = gridDim.x * blockDim.x * 4;
    int total4 = total & ~3;
    for (int base = (blockIdx.x * blockDim.x + threadIdx.x) * 4; base < total4;
         base += stride) {
        float4 zv = *(const float4*)(z + base);
        int hw = base & (HWDIM - 1);            // 4 elems stay in one (b,c) row
        int c  = (base >> 12) & (CDIM - 1);
        int b  = base >> 19;
        int n  = b * HWDIM + hw;
        float q0 = cb[(size_t)g_idx[n + 0] * CDIM + c];
        float q1 = cb[(size_t)g_idx[n + 1] * CDIM + c];
        float q2 = cb[(size_t)g_idx[n + 2] * CDIM + c];
        float q3 = cb[(size_t)g_idx[n + 3] * CDIM + c];
        float4 o;
        o.x = __fadd_rn(zv.x, __fsub_rn(q0, zv.x));   // exact STE rounding
        o.y = __fadd_rn(zv.y, __fsub_rn(q1, zv.y));
        o.z = __fadd_rn(zv.z, __fsub_rn(q2, zv.z));
        o.w = __fadd_rn(zv.w, __fsub_rn(q3, zv.w));
        *(float4*)(outq + base) = o;
        float d0 = __fsub_rn(zv.x, q0), d1 = __fsub_rn(zv.y, q1);
        float d2 = __fsub_rn(zv.z, q2), d3 = __fsub_rn(zv.w, q3);
        sq += (double)__fmul_rn(d0, d0);
        sq += (double)__fmul_rn(d1, d1);
        sq += (double)__fmul_rn(d2, d2);
        sq += (double)__fmul_rn(d3, d3);
    }
    for (int i = total4 + blockIdx.x * blockDim.x + threadIdx.x; i < total;
         i += gridDim.x * blockDim.x) {
        int hw = i & (HWDIM - 1);
        int c  = (i >> 12) & (CDIM - 1);
        int b  = i >> 19;
        int k  = g_idx[b * HWDIM + hw];
        float zv = z[i];
        float q  = cb[(size_t)k * CDIM + c];
        outq[i]  = __fadd_rn(zv, __fsub_rn(q, zv));
        float d  = __fsub_rn(zv, q);
        sq += (double)__fmul_rn(d, d);
    }
#pragma unroll
    for (int off = 16; off > 0; off >>= 1)
        sq += __shfl_down_sync(0xffffffffu, sq, off);
    int warp = threadIdx.x >> 5;
    if ((threadIdx.x & 31) == 0) sh[warp] = sq;
    __syncthreads();
    if (threadIdx.x == 0) {
        double s = 0.0;
        for (int w = 0; w < 8; w++) s += sh[w];   // fixed order -> deterministic
        g_partials[blockIdx.x] = s;
    }
}

// ------------------------------------------------------------------
__global__ void hist_kernel(float* __restrict__ idx_out, int npix, int write_out) {
    __shared__ int h[KCODES];
    float* dst = write_out ? idx_out : g_idx_scratch;
    for (int i = threadIdx.x; i < KCODES; i += blockDim.x) h[i] = 0;
    __syncthreads();
    for (int n = blockIdx.x * blockDim.x + threadIdx.x; n < npix;
         n += gridDim.x * blockDim.x) {
        int k = g_idx[n];
        atomicAdd(&h[k], 1);
        dst[n] = (float)k;
    }
    __syncthreads();
    for (int i = threadIdx.x; i < KCODES; i += blockDim.x)
        if (h[i]) atomicAdd(&g_counts[i], h[i]);
}

// ------------------------------------------------------------------
__global__ void finalize_kernel(float* __restrict__ out2, int nblocks,
                                double inv_total, int npix) {
    __shared__ double sh[256];
    __shared__ double sh2[256];
    double s = 0.0;
    for (int i = threadIdx.x; i < nblocks; i += 256) s += g_partials[i];
    double h = 0.0;
    double inv_n = 1.0 / (double)npix;
    for (int k = threadIdx.x; k < KCODES; k += 256) {
        double p = (double)g_counts[k] * inv_n;
        h -= p * log(p + 1e-10);
    }
    sh[threadIdx.x]  = s;
    sh2[threadIdx.x] = h;
    __syncthreads();
    for (int st = 128; st > 0; st >>= 1) {
        if (threadIdx.x < st) {
            sh[threadIdx.x]  += sh[threadIdx.x + st];
            sh2[threadIdx.x] += sh2[threadIdx.x + st];
        }
        __syncthreads();
    }
    if (threadIdx.x == 0) {
        double mse = sh[0] * inv_total;
        float m  = (float)mse;
        out2[0] = __fadd_rn(m, __fmul_rn(0.25f, m));
        out2[1] = (float)exp(sh2[0]);
    }
}

// ------------------------------------------------------------------
// Output layout (all float32): [quantized (total) | indices (npix) |
// vq_loss (1) | perplexity (1)] — guarded by out_size.
// ------------------------------------------------------------------
extern "C" void kernel_launch(void* const* d_in, const int* in_sizes, int n_in,
                              void* d_out, int out_size) {
    const float* z  = (const float*)d_in[0];
    const float* cb = (const float*)d_in[1];
    float* out = (float*)d_out;

    int total = in_sizes[0];          // 8388608
    int npix  = total / CDIM;         // 65536

    zero_counts_kernel<<<(KCODES + 255) / 256, 256>>>();
    zz_kernel<<<(npix + 255) / 256, 256>>>(z, npix);
    ee_kernel<<<(KCODES + 255) / 256, 256>>>(cb);
    argmin_kernel<<<npix / 64, 256>>>(z, cb);
    quant_kernel<<<PBLOCKS, 256>>>(z, cb, out, total);

    int write_idx = (out_size >= total + npix) ? 1 : 0;
    hist_kernel<<<64, 256>>>(out + total, npix, write_idx);

    if (out_size >= total + npix + 2) {
        finalize_kernel<<<1, 256>>>(out + total + npix, PBLOCKS,
                                    1.0 / (double)total, npix);
    }
    (void)n_in;
}